// round 16
// baseline (speedup 1.0000x reference)
#include <cuda_runtime.h>
#include <cuda_fp16.h>
#include <cstdint>

#define RESULT_ELEMS 16777216   // 64*256*32*32

// smem layout (bytes)
#define OFF_XH    0        // x hi [128][64] half swizzled, 16384
#define OFF_XL    16384    // x lo, 16384
#define OFF_EB    32768    // E-hi double buffer: buf b at +b*8192
#define OFF_H     49152    // 512 floats
#define OFF_RMAX  51200    // 128 floats (reused as int k at the end)
#define OFF_W     51712    // 128 floats (pruning window per row)
#define OFF_RBEST 52224    // 128 u64 (packed best score/key)
#define OFF_LIST  53248    // 1536 u32 candidates
#define OFF_CNT   59392    // int counter (padded)
#define OFF_BP    59520    // 256 float2 partial |xl|,|xh| sums
#define SMEM_SZ   61568
#define CAP       1536

__device__ float  g_h[512];        // 0.5*||e_k||^2 (exact fp32)
__device__ __half gEh[512 * 64];   // E hi, [n][k]
__device__ __half gEl[512 * 64];   // E lo, [n][k]

__device__ __forceinline__ uint32_t smem_u32(const void* p) {
    uint32_t a;
    asm("{ .reg .u64 t; cvta.to.shared.u64 t, %1; cvt.u32.u64 %0, t; }" : "=r"(a) : "l"(p));
    return a;
}
__device__ __forceinline__ uint32_t sw(uint32_t b) { return b ^ ((b >> 3) & 0x70); }

__device__ __forceinline__ void cpasync16(uint32_t dst, const void* src) {
    asm volatile("cp.async.cg.shared.global [%0], [%1], 16;"
                 :: "r"(dst), "l"(src) : "memory");
}
#define CP_COMMIT() asm volatile("cp.async.commit_group;" ::: "memory")
#define CP_WAIT1()  asm volatile("cp.async.wait_group 1;" ::: "memory")

__device__ __forceinline__ void ldsm4(uint32_t r[4], uint32_t addr) {
    asm volatile("ldmatrix.sync.aligned.m8n8.x4.shared.b16 {%0,%1,%2,%3}, [%4];"
                 : "=r"(r[0]), "=r"(r[1]), "=r"(r[2]), "=r"(r[3]) : "r"(addr));
}
__device__ __forceinline__ void mma16816(float c[4], const uint32_t a[4],
                                         uint32_t b0, uint32_t b1) {
    asm volatile("mma.sync.aligned.m16n8k16.row.col.f32.f16.f16.f32 "
                 "{%0,%1,%2,%3}, {%4,%5,%6,%7}, {%8,%9}, {%0,%1,%2,%3};"
                 : "+f"(c[0]), "+f"(c[1]), "+f"(c[2]), "+f"(c[3])
                 : "r"(a[0]), "r"(a[1]), "r"(a[2]), "r"(a[3]), "r"(b0), "r"(b1));
}

// Fast prep: coalesced loads AND stores via smem transpose.
__global__ __launch_bounds__(256) void prep_kernel(const float* __restrict__ w) {
    __shared__ float s[32][65];
    const int tid = threadIdx.x;
    const int n0  = blockIdx.x * 32;
    {
        int j = tid & 31;
        int c = tid >> 5;
        #pragma unroll
        for (int it = 0; it < 8; ++it, c += 8)
            s[j][c] = w[c * 512 + n0 + j];
    }
    __syncthreads();
    if (tid < 32) {
        float acc = 0.f;
        #pragma unroll
        for (int c = 0; c < 64; ++c) { float v = s[tid][c]; acc = fmaf(v, v, acc); }
        g_h[n0 + tid] = 0.5f * acc;
    }
    {
        int j  = tid >> 3;
        int c0 = (tid & 7) * 8;
        __half hv[8], lv[8];
        #pragma unroll
        for (int i = 0; i < 8; ++i) {
            float v = s[j][c0 + i];
            __half h = __float2half_rn(v);
            hv[i] = h;
            lv[i] = __float2half_rn(v - __half2float(h));
        }
        *(uint4*)(gEh + (n0 + j) * 64 + c0) = *(uint4*)hv;
        *(uint4*)(gEl + (n0 + j) * 64 + c0) = *(uint4*)lv;
    }
}

__global__ __launch_bounds__(256, 3)
void vq_mma(const float* __restrict__ x, const float* __restrict__ w,
            float* __restrict__ out) {
    extern __shared__ char smem[];
    const uint32_t sb = smem_u32(smem);
    float*  hsm   = (float*)(smem + OFF_H);
    float*  rmax  = (float*)(smem + OFF_RMAX);
    float*  Wsm   = (float*)(smem + OFF_W);
    unsigned long long* rbest = (unsigned long long*)(smem + OFF_RBEST);
    uint32_t* list = (uint32_t*)(smem + OFF_LIST);
    int*    cnt   = (int*)(smem + OFF_CNT);
    float2* Bp    = (float2*)(smem + OFF_BP);

    const int tid = threadIdx.x;
    const int bg  = blockIdx.x >> 3;             // b*4+g
    const int mt  = blockIdx.x & 7;
    const int hw0 = mt * 128;

    // ---- async copy of E-hi chunk 0 ----
    {
        #pragma unroll
        for (int i = 0; i < 2; ++i) {
            int u = tid + i * 256;
            int r = u >> 3, seg = u & 7;
            uint32_t off = sw((uint32_t)(r * 128 + seg * 16));
            cpasync16(sb + OFF_EB + off, (const char*)(gEh + r * 64) + seg * 16);
        }
        CP_COMMIT();
    }

    // ---- split x tile to fp16 hi/lo + per-row error-bound partials ----
    const float* xb = x + (size_t)bg * 65536 + hw0;
    {
        int m  = tid & 127;
        int c0 = (tid >> 7) * 16;
        float sxl = 0.f, sxh = 0.f;
        #pragma unroll
        for (int i = 0; i < 16; ++i) {
            int c2 = c0 + i;
            float v0 = xb[(size_t)(2 * c2) * 1024 + m];
            float v1 = xb[(size_t)(2 * c2 + 1) * 1024 + m];
            __half h0 = __float2half_rn(v0), h1 = __float2half_rn(v1);
            float l0 = v0 - __half2float(h0);
            float l1 = v1 - __half2float(h1);
            sxl += fabsf(l0) + fabsf(l1);
            sxh += fabsf(v0) + fabsf(v1);
            uint32_t off = sw((uint32_t)(m * 128 + c2 * 4));
            *(__half2*)(smem + OFF_XH + off) = __halves2half2(h0, h1);
            *(__half2*)(smem + OFF_XL + off) =
                __halves2half2(__float2half_rn(l0), __float2half_rn(l1));
        }
        Bp[tid] = make_float2(sxl, sxh);
    }
    hsm[tid]       = g_h[tid];
    hsm[tid + 256] = g_h[tid + 256];
    if (tid == 0) *cnt = 0;
    __syncthreads();

    if (tid < 128) {
        float2 a = Bp[tid], b = Bp[tid + 128];
        float sxl = a.x + b.x, sxh = a.y + b.y;
        // sound window: 2*( |xl|.(|eh|+|el|) + |xh|.|el| + mma rounding )
        Wsm[tid] = 2.f * (sxl * 1.003f + sxh * 2.8e-4f) + 1e-4f;
        rbest[tid] = 0ULL;
    }

    const int w8 = tid >> 5, lane = tid & 31;
    const int m0 = w8 * 16;
    const int group = lane >> 2, tig = lane & 3;

    // ---- A hi fragments only: 4 ksteps = 16 regs ----
    uint32_t ah[4][4];
    {
        uint32_t arow = (uint32_t)(m0 + (lane & 15));
        uint32_t acol = (uint32_t)((lane >> 4) * 16);
        #pragma unroll
        for (int ks = 0; ks < 4; ++ks) {
            uint32_t off = sw(arow * 128 + (uint32_t)ks * 32 + acol);
            ldsm4(ah[ks], sb + OFF_XH + off);
        }
    }

    const uint32_t brow_l = (uint32_t)((lane & 7) + ((lane >> 4) & 1) * 8);
    const uint32_t bcol_l = (uint32_t)(((lane >> 3) & 1) * 16);

    // ================= PASS A: hi.hi approx, per-row max =================
    float v0m = -3.4e38f, v1m = -3.4e38f;
    #pragma unroll 1
    for (int ch = 0; ch < 8; ++ch) {
        {   // prefetch (ch+1)&7 — at ch==7 this preloads chunk 0 for pass B
            int nx = (ch + 1) & 7;
            uint32_t dst = sb + OFF_EB + (uint32_t)((ch + 1) & 1) * 8192;
            #pragma unroll
            for (int i = 0; i < 2; ++i) {
                int u = tid + i * 256;
                int r = u >> 3, seg = u & 7;
                uint32_t off = sw((uint32_t)(r * 128 + seg * 16));
                cpasync16(dst + off, (const char*)(gEh + (nx * 64 + r) * 64) + seg * 16);
            }
        }
        CP_COMMIT();
        CP_WAIT1();
        __syncthreads();
        const uint32_t ebase = sb + OFF_EB + (uint32_t)(ch & 1) * 8192;
        #pragma unroll
        for (int jp = 0; jp < 4; ++jp) {
            float c0[4] = {0, 0, 0, 0};
            float c1[4] = {0, 0, 0, 0};
            #pragma unroll
            for (int ks = 0; ks < 4; ++ks) {
                uint32_t boff = sw((uint32_t)(jp * 16 + brow_l) * 128 +
                                   (uint32_t)ks * 32 + bcol_l);
                uint32_t bh[4];
                ldsm4(bh, ebase + boff);
                mma16816(c0, ah[ks], bh[0], bh[1]);
                mma16816(c1, ah[ks], bh[2], bh[3]);
            }
            int nb = ch * 64 + jp * 16;
            float h0 = hsm[nb + 2 * tig];
            float h1 = hsm[nb + 2 * tig + 1];
            float h2 = hsm[nb + 8 + 2 * tig];
            float h3 = hsm[nb + 8 + 2 * tig + 1];
            v0m = fmaxf(v0m, fmaxf(fmaxf(c0[0] - h0, c0[1] - h1),
                                   fmaxf(c1[0] - h2, c1[1] - h3)));
            v1m = fmaxf(v1m, fmaxf(fmaxf(c0[2] - h0, c0[3] - h1),
                                   fmaxf(c1[2] - h2, c1[3] - h3)));
        }
        __syncthreads();
    }
    // per-row max across the 4 n-lanes
    #pragma unroll
    for (int off = 1; off <= 2; off <<= 1) {
        v0m = fmaxf(v0m, __shfl_xor_sync(0xffffffffu, v0m, off));
        v1m = fmaxf(v1m, __shfl_xor_sync(0xffffffffu, v1m, off));
    }
    if (tig == 0) {
        rmax[m0 + group]     = v0m;
        rmax[m0 + group + 8] = v1m;
    }
    __syncthreads();
    const float t0 = rmax[m0 + group]     - Wsm[m0 + group];
    const float t1 = rmax[m0 + group + 8] - Wsm[m0 + group + 8];
    const int   r0 = m0 + group, r1 = m0 + group + 8;

    // ================= PASS B: same MMAs, collect candidates =================
    #pragma unroll 1
    for (int ch = 0; ch < 8; ++ch) {
        if (ch < 7) {
            uint32_t dst = sb + OFF_EB + (uint32_t)((ch + 1) & 1) * 8192;
            #pragma unroll
            for (int i = 0; i < 2; ++i) {
                int u = tid + i * 256;
                int r = u >> 3, seg = u & 7;
                uint32_t off = sw((uint32_t)(r * 128 + seg * 16));
                cpasync16(dst + off, (const char*)(gEh + ((ch + 1) * 64 + r) * 64) + seg * 16);
            }
        }
        CP_COMMIT();
        CP_WAIT1();
        __syncthreads();
        const uint32_t ebase = sb + OFF_EB + (uint32_t)(ch & 1) * 8192;
        #pragma unroll
        for (int jp = 0; jp < 4; ++jp) {
            float c0[4] = {0, 0, 0, 0};
            float c1[4] = {0, 0, 0, 0};
            #pragma unroll
            for (int ks = 0; ks < 4; ++ks) {
                uint32_t boff = sw((uint32_t)(jp * 16 + brow_l) * 128 +
                                   (uint32_t)ks * 32 + bcol_l);
                uint32_t bh[4];
                ldsm4(bh, ebase + boff);
                mma16816(c0, ah[ks], bh[0], bh[1]);
                mma16816(c1, ah[ks], bh[2], bh[3]);
            }
            int nb = ch * 64 + jp * 16;
            float h0 = hsm[nb + 2 * tig];
            float h1 = hsm[nb + 2 * tig + 1];
            float h2 = hsm[nb + 8 + 2 * tig];
            float h3 = hsm[nb + 8 + 2 * tig + 1];
            int k0 = nb + 2 * tig, k1 = nb + 2 * tig + 1;
            int k2 = nb + 8 + 2 * tig, k3 = nb + 8 + 2 * tig + 1;
            float s;
            #define PUSH(MM, KK) { int idx = atomicAdd(cnt, 1); \
                if (idx < CAP) list[idx] = ((uint32_t)(MM) << 9) | (uint32_t)(KK); }
            s = c0[0] - h0; if (s >= t0) PUSH(r0, k0);
            s = c0[1] - h1; if (s >= t0) PUSH(r0, k1);
            s = c1[0] - h2; if (s >= t0) PUSH(r0, k2);
            s = c1[1] - h3; if (s >= t0) PUSH(r0, k3);
            s = c0[2] - h0; if (s >= t1) PUSH(r1, k0);
            s = c0[3] - h1; if (s >= t1) PUSH(r1, k1);
            s = c1[2] - h2; if (s >= t1) PUSH(r1, k2);
            s = c1[3] - h3; if (s >= t1) PUSH(r1, k3);
            #undef PUSH
        }
        __syncthreads();
    }

    // ================= exact rescore of candidates (warp-cooperative) =======
    {
        int total = *cnt;
        if (total > CAP) total = CAP;
        for (int i = w8; i < total; i += 8) {
            uint32_t e = list[i];
            int m = (int)(e >> 9), k = (int)(e & 511u);
            uint32_t xoff = sw((uint32_t)(m * 128 + lane * 4));
            float2 xhf = __half22float2(*(__half2*)(smem + OFF_XH + xoff));
            float2 xlf = __half22float2(*(__half2*)(smem + OFF_XL + xoff));
            float2 ehf = __half22float2(((const __half2*)(gEh + k * 64))[lane]);
            float2 elf = __half22float2(((const __half2*)(gEl + k * 64))[lane]);
            float d = (xhf.x + xlf.x) * (ehf.x + elf.x)
                    + (xhf.y + xlf.y) * (ehf.y + elf.y);
            #pragma unroll
            for (int off = 16; off > 0; off >>= 1)
                d += __shfl_xor_sync(0xffffffffu, d, off);
            if (lane == 0) {
                float sc = d - hsm[k];
                uint32_t u = __float_as_uint(sc);
                u = (u & 0x80000000u) ? ~u : (u | 0x80000000u);
                unsigned long long key =
                    ((unsigned long long)u << 32) | (uint32_t)(511 - k);
                atomicMax(&rbest[m], key);
            }
        }
    }
    __syncthreads();

    // decode winners (reuse rmax region as int array)
    int* bki = (int*)(smem + OFF_RMAX);
    if (tid < 128)
        bki[tid] = 511 - (int)(rbest[tid] & 0xffffffffULL);
    __syncthreads();

    // ---- write argmins (as float) ----
    if (tid < 128)
        out[RESULT_ELEMS + bg * 1024 + hw0 + tid] = (float)bki[tid];

    // ---- write result: out[bg*64+c][hw0+m] = w[c][k]*0.5 (coalesced over m) ----
    {
        int m = tid & 127, chh = tid >> 7;
        int k = bki[m];
        float* ob = out + (size_t)bg * 65536 + hw0 + m;
        #pragma unroll
        for (int i = 0; i < 32; ++i) {
            int c = chh + i * 2;
            ob[(size_t)c * 1024] = w[c * 512 + k] * 0.5f;
        }
    }
}

extern "C" void kernel_launch(void* const* d_in, const int* in_sizes, int n_in,
                              void* d_out, int out_size) {
    const float* x = (const float*)d_in[0];   // (64,256,32,32) fp32
    const float* w = (const float*)d_in[1];   // (64,512) fp32
    float* out = (float*)d_out;               // result ++ argmins

    cudaFuncSetAttribute(vq_mma, cudaFuncAttributeMaxDynamicSharedMemorySize, SMEM_SZ);

    prep_kernel<<<16, 256>>>(w);
    vq_mma<<<2048, 256, SMEM_SZ>>>(x, w, out);
}